// round 14
// baseline (speedup 1.0000x reference)
#include <cuda_runtime.h>
#include <cuda_bf16.h>
#include <cstdint>

// TopK(k=64) + sigmoid over rows of [16384, 4096] fp32. One 256-thread CTA/row.
// R14: warp-density restructure. Load loop ONLY pushes candidates
// (v >= 2.0, ~93/row, top-64 superset with P_fail ~1e-3/row) into per-warp
// smem buffers (ticket + 2 STS). Histogram (256 value bins, bin=(v-2)*128)
// is built afterwards in a DENSE 1-slot-per-thread pass (no divergence).
// Warp0 bin search + all-pairs rank-32 give the exact threshold; winners
// scatter-overwrite pre-written zeros. Anomalies (tail<64, warp overflow,
// >32 ties in threshold bin) -> block-uniform exact radix slow path.

constexpr int D    = 4096;
constexpr int T    = 256;
constexpr int KSEL = 64;
constexpr int NB   = 256;    // value bins over [2.0, 4.0], clamp above
constexpr int NW   = 8;      // warps per CTA
constexpr int WCAP = 32;     // per-warp candidate capacity (NW*WCAP == T)

__device__ __forceinline__ uint32_t f2k(uint32_t u) {
    return u ^ ((uint32_t)((int)u >> 31) | 0x80000000u);  // monotonic key
}
__device__ __forceinline__ float k2f(uint32_t k) {
    uint32_t m = (uint32_t)((int)k >> 31);
    return __uint_as_float(k ^ (~m | 0x80000000u));
}
__device__ __forceinline__ float sigm(float f) {
    return __frcp_rn(1.0f + __expf(-f));
}
__device__ __forceinline__ int vbin(float v) {
    // monotone; v>=2.0 -> bin>=0; clamp to NB-1 (FFMA + F2I + IMNMX)
    return min(__float2int_rd(__fmaf_rz(v, 128.0f, -256.0f)), NB - 1);
}

__global__ __launch_bounds__(T, 8)
void topk_sigmoid_kernel(const float* __restrict__ x,
                         float* __restrict__ out) {
    __shared__ __align__(16) int hist[NB];
    __shared__ __align__(16) uint32_t cbk[NW * WCAP];  // raw float bits
    __shared__ __align__(16) uint32_t cbm[NW * WCAP];  // element index
    __shared__ int s_cnt[NW];
    __shared__ uint32_t cand[32];
    __shared__ uint32_t s_bin, s_thr;
    __shared__ int s_remk, s_neq, s_tot, s_n2, s_allt, s_remk2;

    const int row  = blockIdx.x;
    const int tid  = threadIdx.x;
    const int lane = tid & 31;
    const int wrp  = tid >> 5;
    const uint4* __restrict__ x4 =
        reinterpret_cast<const uint4*>(x) + (size_t)row * (D / 4);
    float4* __restrict__ o4 =
        reinterpret_cast<float4*>(out) + (size_t)row * (D / 4);

    hist[tid] = 0;                       // NB == T
    if (tid < NW) s_cnt[tid] = 0;
    if (tid == 0) { s_n2 = 0; s_tot = 0; s_neq = 1 << 30; }
    __syncthreads();

    // ---- 4 front-batched LDG.128 (MLP=4), then 4 STG.128 zeros ----
    uint4 u[4];
    #pragma unroll
    for (int j = 0; j < 4; ++j) u[j] = x4[tid + T * j];
    const float4 z4 = make_float4(0.f, 0.f, 0.f, 0.f);
    #pragma unroll
    for (int j = 0; j < 4; ++j) o4[tid + T * j] = z4;

    // ---- minimal candidate push (no hist, no packing in the hot loop) ----
    #pragma unroll
    for (int j = 0; j < 4; ++j) {
        #pragma unroll
        for (int e = 0; e < 4; ++e) {
            uint32_t ub = (e == 0) ? u[j].x : (e == 1) ? u[j].y
                        : (e == 2) ? u[j].z : u[j].w;
            if (__uint_as_float(ub) >= 2.0f) {       // ~93/4096 per row
                int slot = atomicAdd(&s_cnt[wrp], 1);
                if (slot < WCAP) {
                    cbk[wrp * WCAP + slot] = ub;     // raw bits (positive)
                    cbm[wrp * WCAP + slot] = (uint32_t)(4 * (tid + T * j) + e);
                }
            }
        }
    }
    __syncthreads();

    // ---- dense histogram pass: exactly 1 slot per thread, no divergence ----
    const bool mine = (lane < min(s_cnt[wrp], WCAP));
    const uint32_t myk = cbk[tid];
    const uint32_t myi = cbm[tid];
    const int myb = vbin(__uint_as_float(myk));
    if (mine) atomicAdd(&hist[myb], 1);              // ~93 spread atomics
    __syncthreads();

    // ---- warp0-only bin search over hist[256]; lane owns 8 bins ----
    auto binsearch = [&](int remk) {
        if (wrp == 0) {
            int4 qa = reinterpret_cast<const int4*>(hist)[lane * 2];
            int4 qb = reinterpret_cast<const int4*>(hist)[lane * 2 + 1];
            int tot = qa.x + qa.y + qa.z + qa.w + qb.x + qb.y + qb.z + qb.w;
            int s = tot;  // inclusive suffix over lanes >= mine
            #pragma unroll
            for (int o = 1; o < 32; o <<= 1) {
                int q = __shfl_down_sync(0xFFFFFFFFu, s, o);
                if (lane + o < 32) s += q;
            }
            if (lane == 0) s_tot = s;
            int cum = s - tot;  // count in bins strictly above my 8
            int hh[8] = {qa.x, qa.y, qa.z, qa.w, qb.x, qb.y, qb.z, qb.w};
            #pragma unroll
            for (int j = 7; j >= 0; --j) {
                if (cum < remk && cum + hh[j] >= remk) {  // unique hit
                    s_bin  = (uint32_t)(lane * 8 + j);
                    s_remk = remk - cum;
                    s_neq  = hh[j];
                }
                cum += hh[j];
            }
        }
    };

    binsearch(KSEL);
    __syncthreads();

    bool ovf = false;
    #pragma unroll
    for (int w = 0; w < NW; ++w) ovf |= (s_cnt[w] > WCAP);
    const bool fast = !ovf && (s_tot >= KSEL) && (s_neq <= 32);

    if (fast) {
        const int bsel = (int)s_bin;
        const int remk = s_remk, neq = s_neq;

        // ---- compact threshold-bin keys: 1 slot per thread ----
        if (mine && myb == bsel) {
            int t = atomicAdd(&s_n2, 1);             // ~1-2 pushes per row
            if (t < 32) cand[t] = myk;
        }
        __syncthreads();

        // ---- warp0 all-pairs rank over <=32 keys -> exact threshold ----
        if (wrp == 0) {
            uint32_t mk = (lane < neq) ? cand[lane] : 0u;
            int g = 0, eq = 1;  // eq includes self
            #pragma unroll
            for (int i = 1; i < 32; ++i) {
                uint32_t ok = __shfl_sync(0xFFFFFFFFu, mk, (lane + i) & 31);
                int ol = (lane + i) & 31;
                if (ol < neq) { g += (ok > mk); eq += (ok == mk); }
            }
            if (lane < neq && g < remk && g + eq >= remk) {
                s_thr   = mk;
                s_remk2 = remk - g;
                s_allt  = (eq == remk - g);
            }
        }
        __syncthreads();
        const uint32_t thr = s_thr;
        const bool allt = (s_allt != 0);
        const int remk2 = s_remk2;

        // ---- scatter winners over the pre-written zeros (1 slot/thread) ----
        if (mine && myk >= thr) {
            bool inc = allt || (myk > thr);
            if (!inc) {  // tie at thr: lowest indices first (~never)
                int rk = 0;
                for (int q = 0; q < NW * WCAP; ++q) {
                    if ((q & (WCAP - 1)) < s_cnt[q >> 5] &&
                        cbk[q] == thr && cbm[q] < myi)
                        rk++;
                }
                inc = (rk < remk2);
            }
            if (inc)
                out[(size_t)row * D + myi] = sigm(__uint_as_float(myk));
        }
        return;
    }

    // ---- slow exact path (block-uniform, rare): 8-bit radix over x ----
    {
        uint32_t prefix = 0;
        int shift = 32, remk = KSEL, neq = 0;
        while (true) {
            int w  = (shift < 8) ? shift : 8;
            int ns = shift - w;
            __syncthreads();
            hist[tid] = 0;
            __syncthreads();
            #pragma unroll
            for (int j = 0; j < 4; ++j) {
                #pragma unroll
                for (int e = 0; e < 4; ++e) {
                    uint32_t kk = f2k((e == 0) ? u[j].x : (e == 1) ? u[j].y
                                     : (e == 2) ? u[j].z : u[j].w);
                    bool m = (shift == 32) || ((kk >> shift) == prefix);
                    if (m) atomicAdd(&hist[(kk >> ns) & ((1u << w) - 1u)], 1);
                }
            }
            __syncthreads();
            binsearch(remk);
            __syncthreads();
            prefix = (prefix << w) | s_bin;
            remk = s_remk;
            neq  = s_neq;
            shift = ns;
            if (neq == remk || shift == 0) break;
        }
        uint32_t thr;
        bool allt;
        int remk2 = remk;
        if (neq == remk) { thr = prefix << shift; allt = true; }
        else             { thr = prefix;          allt = false; }

        #pragma unroll
        for (int j = 0; j < 4; ++j) {
            int v4 = tid + T * j;
            float4 r;
            #pragma unroll
            for (int e = 0; e < 4; ++e) {
                uint32_t ub = (e == 0) ? u[j].x : (e == 1) ? u[j].y
                            : (e == 2) ? u[j].z : u[j].w;
                uint32_t kk = f2k(ub);
                float o = 0.f;
                if (kk >= thr) {
                    bool inc = allt || (kk > thr);
                    if (!inc) {  // index tie-break via global scan (exact)
                        int idx = 4 * v4 + e, rk = 0;
                        const float* xr = x + (size_t)row * D;
                        for (int q = 0; q < idx; ++q)
                            rk += (f2k(__float_as_uint(xr[q])) == thr);
                        inc = (rk < remk2);
                    }
                    if (inc) o = sigm(k2f(kk));
                }
                ((float*)&r)[e] = o;
            }
            o4[v4] = r;
        }
    }
}

extern "C" void kernel_launch(void* const* d_in, const int* in_sizes, int n_in,
                              void* d_out, int out_size) {
    const float* x = (const float*)d_in[0];
    float* out = (float*)d_out;
    int rows = in_sizes[0] / D;
    topk_sigmoid_kernel<<<rows, T>>>(x, out);
}

// round 15
// speedup vs baseline: 1.0593x; 1.0593x over previous
#include <cuda_runtime.h>
#include <cuda_bf16.h>
#include <cstdint>

// TopK(k=64) + sigmoid over rows of [16384, 4096] fp32. One 256-thread CTA/row.
// R15 = R13 (best: 86.1us) + single per-quad ticket atomic.
// Load loop: 4 front-batched LDG.128 (MLP=4), 4 STG.128 zeros, per-quad FMNMX
// group test (max(quad) >= 2.0) guarding the candidate path (v >= 2.0,
// ~93/row, top-64 superset with P_fail ~1e-3/row). A taken quad reserves all
// its slots with ONE atomicAdd (removes the serialized per-element ATOMS
// chain). Candidates go to per-warp smem buffers + 256-bin VALUE hist
// (bin=(v-2)*128, spread, in-loop — R14 proved moving it bursts the L1tex
// queue). Fast path on RAW positive-float bits. Warp0 bin search + all-pairs
// rank-32 give the exact threshold; winners scatter-overwrite their zeros.
// Anomalies (tail<64, warp overflow, >32 ties) -> exact radix slow path.

constexpr int D    = 4096;
constexpr int T    = 256;
constexpr int KSEL = 64;
constexpr int NB   = 256;    // value bins over [2.0, 4.0], clamp above
constexpr int NW   = 8;      // warps per CTA
constexpr int WCAP = 32;     // per-warp candidate capacity (NW*WCAP == T)

__device__ __forceinline__ uint32_t f2k(uint32_t u) {
    return u ^ ((uint32_t)((int)u >> 31) | 0x80000000u);  // monotonic key
}
__device__ __forceinline__ float k2f(uint32_t k) {
    uint32_t m = (uint32_t)((int)k >> 31);
    return __uint_as_float(k ^ (~m | 0x80000000u));
}
__device__ __forceinline__ float sigm(float f) {
    return __frcp_rn(1.0f + __expf(-f));
}
__device__ __forceinline__ int vbin(float v) {
    // monotone; v>=2.0 -> bin>=0; clamp to NB-1 (FFMA + F2I + IMNMX)
    return min(__float2int_rd(__fmaf_rz(v, 128.0f, -256.0f)), NB - 1);
}

__global__ __launch_bounds__(T, 8)
void topk_sigmoid_kernel(const float* __restrict__ x,
                         float* __restrict__ out) {
    __shared__ __align__(16) int hist[NB];
    __shared__ __align__(16) uint32_t cbk[NW * WCAP];  // raw float bits
    __shared__ __align__(16) uint32_t cbm[NW * WCAP];  // (bin<<12) | idx
    __shared__ int s_cnt[NW];
    __shared__ uint32_t cand[32];
    __shared__ uint32_t s_bin, s_thr;
    __shared__ int s_remk, s_neq, s_tot, s_n2, s_allt, s_remk2;

    const int row  = blockIdx.x;
    const int tid  = threadIdx.x;
    const int lane = tid & 31;
    const int wrp  = tid >> 5;
    const uint4* __restrict__ x4 =
        reinterpret_cast<const uint4*>(x) + (size_t)row * (D / 4);
    float4* __restrict__ o4 =
        reinterpret_cast<float4*>(out) + (size_t)row * (D / 4);

    hist[tid] = 0;                       // NB == T
    if (tid < NW) s_cnt[tid] = 0;
    if (tid == 0) { s_n2 = 0; s_tot = 0; s_neq = 1 << 30; }
    __syncthreads();

    // ---- 4 front-batched LDG.128 (MLP=4), then 4 STG.128 zeros ----
    uint4 u[4];
    #pragma unroll
    for (int j = 0; j < 4; ++j) u[j] = x4[tid + T * j];
    const float4 z4 = make_float4(0.f, 0.f, 0.f, 0.f);
    #pragma unroll
    for (int j = 0; j < 4; ++j) o4[tid + T * j] = z4;

    // ---- per-quad group test; taken quad reserves slots with ONE atomic ----
    #pragma unroll
    for (int j = 0; j < 4; ++j) {
        const float fx = __uint_as_float(u[j].x);
        const float fy = __uint_as_float(u[j].y);
        const float fz = __uint_as_float(u[j].z);
        const float fw = __uint_as_float(u[j].w);
        const float mx = fmaxf(fmaxf(fx, fy), fmaxf(fz, fw));
        if (mx >= 2.0f) {                            // ~8.8% of thread-quads
            const bool c0 = (fx >= 2.0f), c1 = (fy >= 2.0f);
            const bool c2 = (fz >= 2.0f), c3 = (fw >= 2.0f);
            const int cnt = (int)c0 + (int)c1 + (int)c2 + (int)c3;  // >= 1
            int p = atomicAdd(&s_cnt[wrp], cnt);     // one ticket per quad
            const int ib = 4 * (tid + T * j);
            if (c0) {
                if (p < WCAP) {
                    cbk[wrp * WCAP + p] = u[j].x;
                    cbm[wrp * WCAP + p] = ((uint32_t)vbin(fx) << 12) | (ib + 0);
                }
                atomicAdd(&hist[vbin(fx)], 1);
                ++p;
            }
            if (c1) {
                if (p < WCAP) {
                    cbk[wrp * WCAP + p] = u[j].y;
                    cbm[wrp * WCAP + p] = ((uint32_t)vbin(fy) << 12) | (ib + 1);
                }
                atomicAdd(&hist[vbin(fy)], 1);
                ++p;
            }
            if (c2) {
                if (p < WCAP) {
                    cbk[wrp * WCAP + p] = u[j].z;
                    cbm[wrp * WCAP + p] = ((uint32_t)vbin(fz) << 12) | (ib + 2);
                }
                atomicAdd(&hist[vbin(fz)], 1);
                ++p;
            }
            if (c3) {
                if (p < WCAP) {
                    cbk[wrp * WCAP + p] = u[j].w;
                    cbm[wrp * WCAP + p] = ((uint32_t)vbin(fw) << 12) | (ib + 3);
                }
                atomicAdd(&hist[vbin(fw)], 1);
                ++p;
            }
        }
    }
    __syncthreads();

    // ---- warp0-only bin search over hist[256]; lane owns 8 bins ----
    auto binsearch = [&](int remk) {
        if (wrp == 0) {
            int4 qa = reinterpret_cast<const int4*>(hist)[lane * 2];
            int4 qb = reinterpret_cast<const int4*>(hist)[lane * 2 + 1];
            int tot = qa.x + qa.y + qa.z + qa.w + qb.x + qb.y + qb.z + qb.w;
            int s = tot;  // inclusive suffix over lanes >= mine
            #pragma unroll
            for (int o = 1; o < 32; o <<= 1) {
                int q = __shfl_down_sync(0xFFFFFFFFu, s, o);
                if (lane + o < 32) s += q;
            }
            if (lane == 0) s_tot = s;
            int cum = s - tot;  // count in bins strictly above my 8
            int hh[8] = {qa.x, qa.y, qa.z, qa.w, qb.x, qb.y, qb.z, qb.w};
            #pragma unroll
            for (int j = 7; j >= 0; --j) {
                if (cum < remk && cum + hh[j] >= remk) {  // unique hit
                    s_bin  = (uint32_t)(lane * 8 + j);
                    s_remk = remk - cum;
                    s_neq  = hh[j];
                }
                cum += hh[j];
            }
        }
    };

    binsearch(KSEL);
    __syncthreads();

    bool ovf = false;
    #pragma unroll
    for (int w = 0; w < NW; ++w) ovf |= (s_cnt[w] > WCAP);
    const bool fast = !ovf && (s_tot >= KSEL) && (s_neq <= 32);

    if (fast) {
        const uint32_t bsel = s_bin;
        const int remk = s_remk, neq = s_neq;

        // ---- compact threshold-bin keys: exactly 1 slot per thread ----
        const bool mine = (lane < s_cnt[wrp]);
        const uint32_t mym = cbm[tid];
        const uint32_t myk = cbk[tid];
        if (mine && (mym >> 12) == bsel) {
            int t = atomicAdd(&s_n2, 1);             // ~1-2 pushes per row
            if (t < 32) cand[t] = myk;
        }
        __syncthreads();

        // ---- warp0 all-pairs rank over <=32 keys -> exact threshold ----
        if (wrp == 0) {
            uint32_t mk = (lane < neq) ? cand[lane] : 0u;
            int g = 0, eq = 1;  // eq includes self
            #pragma unroll
            for (int i = 1; i < 32; ++i) {
                uint32_t ok = __shfl_sync(0xFFFFFFFFu, mk, (lane + i) & 31);
                int ol = (lane + i) & 31;
                if (ol < neq) { g += (ok > mk); eq += (ok == mk); }
            }
            if (lane < neq && g < remk && g + eq >= remk) {
                s_thr   = mk;
                s_remk2 = remk - g;
                s_allt  = (eq == remk - g);
            }
        }
        __syncthreads();
        const uint32_t thr = s_thr;
        const bool allt = (s_allt != 0);
        const int remk2 = s_remk2;

        // ---- scatter winners over the pre-written zeros (1 slot/thread) ----
        if (mine && myk >= thr) {
            bool inc = allt || (myk > thr);
            if (!inc) {  // tie at thr: lowest indices first (~never)
                uint32_t myi = mym & 0xFFFu;
                int rk = 0;
                for (int q = 0; q < NW * WCAP; ++q) {
                    if ((q & (WCAP - 1)) < s_cnt[q >> 5] &&
                        cbk[q] == thr && (cbm[q] & 0xFFFu) < myi)
                        rk++;
                }
                inc = (rk < remk2);
            }
            if (inc)
                out[(size_t)row * D + (mym & 0xFFFu)] =
                    sigm(__uint_as_float(myk));
        }
        return;
    }

    // ---- slow exact path (block-uniform, rare): 8-bit radix over x ----
    {
        uint32_t prefix = 0;
        int shift = 32, remk = KSEL, neq = 0;
        while (true) {
            int w  = (shift < 8) ? shift : 8;
            int ns = shift - w;
            __syncthreads();
            hist[tid] = 0;
            __syncthreads();
            #pragma unroll
            for (int j = 0; j < 4; ++j) {
                #pragma unroll
                for (int e = 0; e < 4; ++e) {
                    uint32_t kk = f2k((e == 0) ? u[j].x : (e == 1) ? u[j].y
                                     : (e == 2) ? u[j].z : u[j].w);
                    bool m = (shift == 32) || ((kk >> shift) == prefix);
                    if (m) atomicAdd(&hist[(kk >> ns) & ((1u << w) - 1u)], 1);
                }
            }
            __syncthreads();
            binsearch(remk);
            __syncthreads();
            prefix = (prefix << w) | s_bin;
            remk = s_remk;
            neq  = s_neq;
            shift = ns;
            if (neq == remk || shift == 0) break;
        }
        uint32_t thr;
        bool allt;
        int remk2 = remk;
        if (neq == remk) { thr = prefix << shift; allt = true; }
        else             { thr = prefix;          allt = false; }

        #pragma unroll
        for (int j = 0; j < 4; ++j) {
            int v4 = tid + T * j;
            float4 r;
            #pragma unroll
            for (int e = 0; e < 4; ++e) {
                uint32_t ub = (e == 0) ? u[j].x : (e == 1) ? u[j].y
                            : (e == 2) ? u[j].z : u[j].w;
                uint32_t kk = f2k(ub);
                float o = 0.f;
                if (kk >= thr) {
                    bool inc = allt || (kk > thr);
                    if (!inc) {  // index tie-break via global scan (exact)
                        int idx = 4 * v4 + e, rk = 0;
                        const float* xr = x + (size_t)row * D;
                        for (int q = 0; q < idx; ++q)
                            rk += (f2k(__float_as_uint(xr[q])) == thr);
                        inc = (rk < remk2);
                    }
                    if (inc) o = sigm(k2f(kk));
                }
                ((float*)&r)[e] = o;
            }
            o4[v4] = r;
        }
    }
}

extern "C" void kernel_launch(void* const* d_in, const int* in_sizes, int n_in,
                              void* d_out, int out_size) {
    const float* x = (const float*)d_in[0];
    float* out = (float*)d_out;
    int rows = in_sizes[0] / D;
    topk_sigmoid_kernel<<<rows, T>>>(x, out);
}

// round 16
// speedup vs baseline: 1.0835x; 1.0229x over previous
#include <cuda_runtime.h>
#include <cuda_bf16.h>
#include <cstdint>

// TopK(k=64) + sigmoid over rows of [16384, 4096] fp32. One 256-thread CTA/row.
// R16 = R13 (best: 86.1us) + __ldcs streaming loads (input is read-once;
// evict-first keeps dead input lines from competing with the output stream
// in L2). Load loop: 4 front-batched LDG.128 (MLP=4), 4 STG.128 zeros,
// per-quad FMNMX group test (max(quad) >= 2.0) guarding the per-element
// candidate path (v >= 2.0, ~93/row, top-64 superset with P_fail ~1e-3/row).
// Candidates: per-warp atomic ticket into smem buffers + 256-bin VALUE hist
// (bin=(v-2)*128, spread, in-loop). Fast path on RAW positive-float bits.
// Warp0 bin search + all-pairs rank-32 give the exact threshold; winners
// scatter-overwrite their zeros. Anomalies (tail<64, warp overflow, >32
// ties in threshold bin) -> block-uniform exact radix slow path.

constexpr int D    = 4096;
constexpr int T    = 256;
constexpr int KSEL = 64;
constexpr int NB   = 256;    // value bins over [2.0, 4.0], clamp above
constexpr int NW   = 8;      // warps per CTA
constexpr int WCAP = 32;     // per-warp candidate capacity (NW*WCAP == T)

__device__ __forceinline__ uint32_t f2k(uint32_t u) {
    return u ^ ((uint32_t)((int)u >> 31) | 0x80000000u);  // monotonic key
}
__device__ __forceinline__ float k2f(uint32_t k) {
    uint32_t m = (uint32_t)((int)k >> 31);
    return __uint_as_float(k ^ (~m | 0x80000000u));
}
__device__ __forceinline__ float sigm(float f) {
    return __frcp_rn(1.0f + __expf(-f));
}
__device__ __forceinline__ int vbin(float v) {
    // monotone; v>=2.0 -> bin>=0; clamp to NB-1 (FFMA + F2I + IMNMX)
    return min(__float2int_rd(__fmaf_rz(v, 128.0f, -256.0f)), NB - 1);
}

__global__ __launch_bounds__(T, 8)
void topk_sigmoid_kernel(const float* __restrict__ x,
                         float* __restrict__ out) {
    __shared__ __align__(16) int hist[NB];
    __shared__ __align__(16) uint32_t cbk[NW * WCAP];  // raw float bits
    __shared__ __align__(16) uint32_t cbm[NW * WCAP];  // (bin<<12) | idx
    __shared__ int s_cnt[NW];
    __shared__ uint32_t cand[32];
    __shared__ uint32_t s_bin, s_thr;
    __shared__ int s_remk, s_neq, s_tot, s_n2, s_allt, s_remk2;

    const int row  = blockIdx.x;
    const int tid  = threadIdx.x;
    const int lane = tid & 31;
    const int wrp  = tid >> 5;
    const uint4* __restrict__ x4 =
        reinterpret_cast<const uint4*>(x) + (size_t)row * (D / 4);
    float4* __restrict__ o4 =
        reinterpret_cast<float4*>(out) + (size_t)row * (D / 4);

    hist[tid] = 0;                       // NB == T
    if (tid < NW) s_cnt[tid] = 0;
    if (tid == 0) { s_n2 = 0; s_tot = 0; s_neq = 1 << 30; }
    __syncthreads();

    // ---- 4 front-batched streaming LDG.128 (MLP=4), then 4 STG.128 zeros ----
    uint4 u[4];
    #pragma unroll
    for (int j = 0; j < 4; ++j) u[j] = __ldcs(&x4[tid + T * j]);
    const float4 z4 = make_float4(0.f, 0.f, 0.f, 0.f);
    #pragma unroll
    for (int j = 0; j < 4; ++j) o4[tid + T * j] = z4;

    // ---- per-quad group test, rare per-element candidate path ----
    #pragma unroll
    for (int j = 0; j < 4; ++j) {
        const float fx = __uint_as_float(u[j].x);
        const float fy = __uint_as_float(u[j].y);
        const float fz = __uint_as_float(u[j].z);
        const float fw = __uint_as_float(u[j].w);
        const float mx = fmaxf(fmaxf(fx, fy), fmaxf(fz, fw));
        if (mx >= 2.0f) {                            // ~8.8% of thread-quads
            #pragma unroll
            for (int e = 0; e < 4; ++e) {
                uint32_t ub = (e == 0) ? u[j].x : (e == 1) ? u[j].y
                            : (e == 2) ? u[j].z : u[j].w;
                float vv = __uint_as_float(ub);
                if (vv >= 2.0f) {                    // ~93/4096 per row
                    int b = vbin(vv);
                    atomicAdd(&hist[b], 1);          // spread: <1 key/bin
                    int slot = atomicAdd(&s_cnt[wrp], 1);  // ~12/warp
                    if (slot < WCAP) {
                        cbk[wrp * WCAP + slot] = ub; // raw bits (positive)
                        cbm[wrp * WCAP + slot] =
                            ((uint32_t)b << 12) |
                            (uint32_t)(4 * (tid + T * j) + e);
                    }
                }
            }
        }
    }
    __syncthreads();

    // ---- warp0-only bin search over hist[256]; lane owns 8 bins ----
    auto binsearch = [&](int remk) {
        if (wrp == 0) {
            int4 qa = reinterpret_cast<const int4*>(hist)[lane * 2];
            int4 qb = reinterpret_cast<const int4*>(hist)[lane * 2 + 1];
            int tot = qa.x + qa.y + qa.z + qa.w + qb.x + qb.y + qb.z + qb.w;
            int s = tot;  // inclusive suffix over lanes >= mine
            #pragma unroll
            for (int o = 1; o < 32; o <<= 1) {
                int q = __shfl_down_sync(0xFFFFFFFFu, s, o);
                if (lane + o < 32) s += q;
            }
            if (lane == 0) s_tot = s;
            int cum = s - tot;  // count in bins strictly above my 8
            int hh[8] = {qa.x, qa.y, qa.z, qa.w, qb.x, qb.y, qb.z, qb.w};
            #pragma unroll
            for (int j = 7; j >= 0; --j) {
                if (cum < remk && cum + hh[j] >= remk) {  // unique hit
                    s_bin  = (uint32_t)(lane * 8 + j);
                    s_remk = remk - cum;
                    s_neq  = hh[j];
                }
                cum += hh[j];
            }
        }
    };

    binsearch(KSEL);
    __syncthreads();

    bool ovf = false;
    #pragma unroll
    for (int w = 0; w < NW; ++w) ovf |= (s_cnt[w] > WCAP);
    const bool fast = !ovf && (s_tot >= KSEL) && (s_neq <= 32);

    if (fast) {
        const uint32_t bsel = s_bin;
        const int remk = s_remk, neq = s_neq;

        // ---- compact threshold-bin keys: exactly 1 slot per thread ----
        const bool mine = (lane < s_cnt[wrp]);
        const uint32_t mym = cbm[tid];
        const uint32_t myk = cbk[tid];
        if (mine && (mym >> 12) == bsel) {
            int t = atomicAdd(&s_n2, 1);             // ~1-2 pushes per row
            if (t < 32) cand[t] = myk;
        }
        __syncthreads();

        // ---- warp0 all-pairs rank over <=32 keys -> exact threshold ----
        if (wrp == 0) {
            uint32_t mk = (lane < neq) ? cand[lane] : 0u;
            int g = 0, eq = 1;  // eq includes self
            #pragma unroll
            for (int i = 1; i < 32; ++i) {
                uint32_t ok = __shfl_sync(0xFFFFFFFFu, mk, (lane + i) & 31);
                int ol = (lane + i) & 31;
                if (ol < neq) { g += (ok > mk); eq += (ok == mk); }
            }
            if (lane < neq && g < remk && g + eq >= remk) {
                s_thr   = mk;
                s_remk2 = remk - g;
                s_allt  = (eq == remk - g);
            }
        }
        __syncthreads();
        const uint32_t thr = s_thr;
        const bool allt = (s_allt != 0);
        const int remk2 = s_remk2;

        // ---- scatter winners over the pre-written zeros (1 slot/thread) ----
        if (mine && myk >= thr) {
            bool inc = allt || (myk > thr);
            if (!inc) {  // tie at thr: lowest indices first (~never)
                uint32_t myi = mym & 0xFFFu;
                int rk = 0;
                for (int q = 0; q < NW * WCAP; ++q) {
                    if ((q & (WCAP - 1)) < s_cnt[q >> 5] &&
                        cbk[q] == thr && (cbm[q] & 0xFFFu) < myi)
                        rk++;
                }
                inc = (rk < remk2);
            }
            if (inc)
                out[(size_t)row * D + (mym & 0xFFFu)] =
                    sigm(__uint_as_float(myk));
        }
        return;
    }

    // ---- slow exact path (block-uniform, rare): 8-bit radix over x ----
    {
        uint32_t prefix = 0;
        int shift = 32, remk = KSEL, neq = 0;
        while (true) {
            int w  = (shift < 8) ? shift : 8;
            int ns = shift - w;
            __syncthreads();
            hist[tid] = 0;
            __syncthreads();
            #pragma unroll
            for (int j = 0; j < 4; ++j) {
                #pragma unroll
                for (int e = 0; e < 4; ++e) {
                    uint32_t kk = f2k((e == 0) ? u[j].x : (e == 1) ? u[j].y
                                     : (e == 2) ? u[j].z : u[j].w);
                    bool m = (shift == 32) || ((kk >> shift) == prefix);
                    if (m) atomicAdd(&hist[(kk >> ns) & ((1u << w) - 1u)], 1);
                }
            }
            __syncthreads();
            binsearch(remk);
            __syncthreads();
            prefix = (prefix << w) | s_bin;
            remk = s_remk;
            neq  = s_neq;
            shift = ns;
            if (neq == remk || shift == 0) break;
        }
        uint32_t thr;
        bool allt;
        int remk2 = remk;
        if (neq == remk) { thr = prefix << shift; allt = true; }
        else             { thr = prefix;          allt = false; }

        #pragma unroll
        for (int j = 0; j < 4; ++j) {
            int v4 = tid + T * j;
            float4 r;
            #pragma unroll
            for (int e = 0; e < 4; ++e) {
                uint32_t ub = (e == 0) ? u[j].x : (e == 1) ? u[j].y
                            : (e == 2) ? u[j].z : u[j].w;
                uint32_t kk = f2k(ub);
                float o = 0.f;
                if (kk >= thr) {
                    bool inc = allt || (kk > thr);
                    if (!inc) {  // index tie-break via global scan (exact)
                        int idx = 4 * v4 + e, rk = 0;
                        const float* xr = x + (size_t)row * D;
                        for (int q = 0; q < idx; ++q)
                            rk += (f2k(__float_as_uint(xr[q])) == thr);
                        inc = (rk < remk2);
                    }
                    if (inc) o = sigm(k2f(kk));
                }
                ((float*)&r)[e] = o;
            }
            o4[v4] = r;
        }
    }
}

extern "C" void kernel_launch(void* const* d_in, const int* in_sizes, int n_in,
                              void* d_out, int out_size) {
    const float* x = (const float*)d_in[0];
    float* out = (float*)d_out;
    int rows = in_sizes[0] / D;
    topk_sigmoid_kernel<<<rows, T>>>(x, out);
}